// round 14
// baseline (speedup 1.0000x reference)
#include <cuda_runtime.h>
#include <cuda_bf16.h>
#include <cuda_fp16.h>
#include <cstdint>

#define NN 50000
#define NE 800000
#define ET 850000   // NE + NN self loops
#define D1 256      // heads(4) * h1(64)
#define D2 128

// ---------------- device scratch (static; no runtime allocation) ----------------
__device__ __align__(16) __half g_xh1h[NN * D1];   // X @ W1 (fp16)
__device__ __align__(16) __half g_xh2h[NN * D2];   // H1 @ W2 (fp16)
__device__ __align__(16) __half g_xf16[NN * 64];    // X as fp16 (gemm1 A)
__device__ __align__(16) __half g_h1f16[NN * D1];   // H1 as fp16 (gemm2 A)
__device__ __align__(16) float g_as1[NN * 4];
__device__ __align__(16) float g_ad1[NN * 4];
__device__ float g_as2[NN];
__device__ float g_ad2[NN];
__device__ int g_deg[NN];
__device__ int g_rowptr[NN + 1];
__device__ int g_rank[ET];
__device__ int g_esrc[ET];
__device__ int g_bsum[64];
// transposed fp16 weights: Wt[n][k]
__device__ __align__(16) __half g_wt1f[D1 * 64];
__device__ __align__(16) __half g_wt2f[D2 * D1];

__device__ __forceinline__ int esrc_of(const int* __restrict__ ei, int e) {
    return e < NE ? ei[e] : e - NE;
}
__device__ __forceinline__ int edst_of(const int* __restrict__ ei, int e) {
    return e < NE ? ei[NE + e] : e - NE;
}
__device__ __forceinline__ float lrelu(float x) { return x > 0.f ? x : 0.2f * x; }

// ---------------- fused prep: zero deg+logits, X fp16, W1/W2 transpose fp16 ----------------
__global__ __launch_bounds__(256) void k_prep(const float* __restrict__ X,
                                              const float* __restrict__ W1,
                                              const float* __restrict__ W2) {
    int i = blockIdx.x * 256 + threadIdx.x;
    if (i < NN) { g_deg[i] = 0; g_as2[i] = 0.f; g_ad2[i] = 0.f; }
    if (i < NN * 4) { g_as1[i] = 0.f; g_ad1[i] = 0.f; }
    if (i < NN * 16) {
        float4 v = ((const float4*)X)[i];
        __half2 h0 = __floats2half2_rn(v.x, v.y);
        __half2 h1 = __floats2half2_rn(v.z, v.w);
        ((uint2*)g_xf16)[i] = make_uint2(*(uint32_t*)&h0, *(uint32_t*)&h1);
    }
    if (i < 64 * D1) {
        int k = i / D1, n = i % D1;
        g_wt1f[n * 64 + k] = __float2half(W1[i]);
    }
    if (i < D1 * D2) {
        int k = i / D2, n = i % D2;
        g_wt2f[n * D1 + k] = __float2half(W2[i]);
    }
}

// ---------------- CSR build ----------------
__global__ void k_count(const int* __restrict__ ei) {
    int e = blockIdx.x * 256 + threadIdx.x;
    if (e < ET) {
        int r = atomicAdd(&g_deg[edst_of(ei, e)], 1);
        g_rank[e] = r;
    }
}

__global__ void k_scan1() {
    __shared__ int s[1024];
    int t = threadIdx.x;
    int i = blockIdx.x * 1024 + t;
    int v = (i < NN) ? g_deg[i] : 0;
    s[t] = v;
    __syncthreads();
    #pragma unroll
    for (int off = 1; off < 1024; off <<= 1) {
        int x = (t >= off) ? s[t - off] : 0;
        __syncthreads();
        s[t] += x;
        __syncthreads();
    }
    if (i < NN) g_rowptr[i] = s[t] - v;
    if (t == 1023) g_bsum[blockIdx.x] = s[t];
}

// scan3 folds the 49-element bsum prefix in itself (removes k_scan2 launch)
__global__ void k_scan3() {
    __shared__ int soff;
    if (threadIdx.x == 0) {
        int a = 0;
        for (int b = 0; b < (int)blockIdx.x; b++) a += g_bsum[b];
        soff = a;
    }
    __syncthreads();
    int i = blockIdx.x * 1024 + threadIdx.x;
    if (i < NN)
        g_rowptr[i] = g_rowptr[i] + soff;
    if (i == 0) g_rowptr[NN] = ET;
}

__global__ void k_fill(const int* __restrict__ ei) {
    int e = blockIdx.x * 256 + threadIdx.x;
    if (e < ET) {
        int d = edst_of(ei, e);
        int s = esrc_of(ei, e);
        g_esrc[g_rowptr[d] + g_rank[e]] = s;
    }
}

// ---------------- HMMA fp16 GEMM + fused attention-logit epilogue ----------------
// C[M,NCOL] = A @ Bt^T (fp16 in/out, fp32 acc). Epilogue also computes per-row
// logits: gAs[r*HEADS+h] += sum_c acc[r][c]*att_s[h][c], same for gAd.
#define KC 32
#define ASTR 40
#define TILE_ELEMS (128 * ASTR)

__device__ __forceinline__ void ldsm4h(uint32_t& r0, uint32_t& r1, uint32_t& r2, uint32_t& r3,
                                       const __half* p) {
    uint32_t a = (uint32_t)__cvta_generic_to_shared(p);
    asm volatile("ldmatrix.sync.aligned.m8n8.x4.shared.b16 {%0,%1,%2,%3}, [%4];"
                 : "=r"(r0), "=r"(r1), "=r"(r2), "=r"(r3) : "r"(a));
}
__device__ __forceinline__ void mmaf16(float* d, uint32_t a0, uint32_t a1, uint32_t a2,
                                       uint32_t a3, uint32_t b0, uint32_t b1) {
    asm volatile(
        "mma.sync.aligned.m16n8k16.row.col.f32.f16.f16.f32 "
        "{%0,%1,%2,%3}, {%4,%5,%6,%7}, {%8,%9}, {%0,%1,%2,%3};"
        : "+f"(d[0]), "+f"(d[1]), "+f"(d[2]), "+f"(d[3])
        : "r"(a0), "r"(a1), "r"(a2), "r"(a3), "r"(b0), "r"(b1));
}
__device__ __forceinline__ void cpa16h(__half* dst, const __half* src) {
    uint32_t d = (uint32_t)__cvta_generic_to_shared(dst);
    asm volatile("cp.async.cg.shared.global [%0], [%1], 16;" :: "r"(d), "l"(src));
}

template<int KTOT, int HEADS>
__global__ __launch_bounds__(256, 2) void k_gemm_f16(const __half* __restrict__ A,
                                                     const __half* __restrict__ Bt,
                                                     __half* __restrict__ C,
                                                     const float* __restrict__ att_s,
                                                     const float* __restrict__ att_d,
                                                     float* __restrict__ gAs,
                                                     float* __restrict__ gAd,
                                                     int M, int NCOL) {
    constexpr int NCH = KTOT / KC;
    extern __shared__ __half smh[];

    int tid = threadIdx.x;
    int wid = tid >> 5, lane = tid & 31;
    int g = lane >> 2, tig = lane & 3;
    int wm = (wid >> 2) * 64;
    int wn = (wid & 3) * 32;
    int bm = blockIdx.y * 128;
    int bn = blockIdx.x * 128;

    float acc[4][4][4];
    #pragma unroll
    for (int mt = 0; mt < 4; mt++)
        #pragma unroll
        for (int nt = 0; nt < 4; nt++)
            #pragma unroll
            for (int f = 0; f < 4; f++) acc[mt][nt][f] = 0.f;

    int a_r = lane & 15, a_c = (lane >> 4) * 8;
    int b_r = (lane >> 4) * 8 + (lane & 7), b_c = ((lane >> 3) & 1) * 8;

    int frow0 = tid >> 2, fcol = (tid & 3) * 8;
    int frow1 = (tid + 256) >> 2;

    auto fill = [&](int s, int c) {
        __half* s_a = smh + (s * 2 + 0) * TILE_ELEMS;
        __half* s_b = smh + (s * 2 + 1) * TILE_ELEMS;
        int kbase = c * KC;
        int ar0 = bm + frow0; if (ar0 >= M) ar0 = M - 1;
        int ar1 = bm + frow1; if (ar1 >= M) ar1 = M - 1;
        cpa16h(&s_a[frow0 * ASTR + fcol], &A[(size_t)ar0 * KTOT + kbase + fcol]);
        cpa16h(&s_a[frow1 * ASTR + fcol], &A[(size_t)ar1 * KTOT + kbase + fcol]);
        cpa16h(&s_b[frow0 * ASTR + fcol], &Bt[(size_t)(bn + frow0) * KTOT + kbase + fcol]);
        cpa16h(&s_b[frow1 * ASTR + fcol], &Bt[(size_t)(bn + frow1) * KTOT + kbase + fcol]);
        asm volatile("cp.async.commit_group;");
    };

    fill(0, 0);
    int stage = 0;
    for (int c = 0; c < NCH; c++) {
        if (c + 1 < NCH) {
            fill(stage ^ 1, c + 1);
            asm volatile("cp.async.wait_group 1;");
        } else {
            asm volatile("cp.async.wait_group 0;");
        }
        __syncthreads();

        __half* s_a = smh + (stage * 2 + 0) * TILE_ELEMS;
        __half* s_b = smh + (stage * 2 + 1) * TILE_ELEMS;

        #pragma unroll
        for (int ks = 0; ks < KC; ks += 16) {
            uint32_t bf[4][2];
            #pragma unroll
            for (int p = 0; p < 2; p++)
                ldsm4h(bf[2*p][0], bf[2*p][1], bf[2*p+1][0], bf[2*p+1][1],
                       &s_b[(wn + p * 16 + b_r) * ASTR + ks + b_c]);
            #pragma unroll
            for (int mt = 0; mt < 4; mt++) {
                uint32_t a0, a1, a2, a3;
                ldsm4h(a0, a1, a2, a3, &s_a[(wm + mt * 16 + a_r) * ASTR + ks + a_c]);
                #pragma unroll
                for (int nt = 0; nt < 4; nt++)
                    mmaf16(acc[mt][nt], a0, a1, a2, a3, bf[nt][0], bf[nt][1]);
            }
        }
        __syncthreads();
        stage ^= 1;
    }

    // epilogue: fp16 feature stores + fused attention logits
    constexpr int CHDIM = 0;  // placeholder (computed at runtime from NCOL/HEADS)
    int chdim = NCOL / HEADS;
    int head = (bn + wn) / chdim;
    int cbase = (bn + wn) % chdim + 2 * tig;

    #pragma unroll
    for (int mt = 0; mt < 4; mt++) {
        int r0 = bm + wm + mt * 16 + g;
        int r1 = r0 + 8;
        float s0 = 0.f, d0 = 0.f, s1 = 0.f, d1 = 0.f;
        #pragma unroll
        for (int nt = 0; nt < 4; nt++) {
            int col = bn + wn + nt * 8 + 2 * tig;
            if (r0 < M) {
                __half2 h = __floats2half2_rn(acc[mt][nt][0], acc[mt][nt][1]);
                *(uint32_t*)&C[(size_t)r0 * NCOL + col] = *(uint32_t*)&h;
            }
            if (r1 < M) {
                __half2 h = __floats2half2_rn(acc[mt][nt][2], acc[mt][nt][3]);
                *(uint32_t*)&C[(size_t)r1 * NCOL + col] = *(uint32_t*)&h;
            }
            int ci = head * chdim + cbase + nt * 8;
            float as0 = att_s[ci], as1v = att_s[ci + 1];
            float ad0 = att_d[ci], ad1v = att_d[ci + 1];
            s0 += acc[mt][nt][0] * as0 + acc[mt][nt][1] * as1v;
            d0 += acc[mt][nt][0] * ad0 + acc[mt][nt][1] * ad1v;
            s1 += acc[mt][nt][2] * as0 + acc[mt][nt][3] * as1v;
            d1 += acc[mt][nt][2] * ad0 + acc[mt][nt][3] * ad1v;
        }
        // reduce over the 4 quad lanes (tig)
        s0 += __shfl_xor_sync(0xffffffffu, s0, 1); s0 += __shfl_xor_sync(0xffffffffu, s0, 2);
        d0 += __shfl_xor_sync(0xffffffffu, d0, 1); d0 += __shfl_xor_sync(0xffffffffu, d0, 2);
        s1 += __shfl_xor_sync(0xffffffffu, s1, 1); s1 += __shfl_xor_sync(0xffffffffu, s1, 2);
        d1 += __shfl_xor_sync(0xffffffffu, d1, 1); d1 += __shfl_xor_sync(0xffffffffu, d1, 2);
        if (tig == 0) {
            if (r0 < M) {
                atomicAdd(&gAs[r0 * HEADS + head], s0);
                atomicAdd(&gAd[r0 * HEADS + head], d0);
            }
            if (r1 < M) {
                atomicAdd(&gAs[r1 * HEADS + head], s1);
                atomicAdd(&gAd[r1 * HEADS + head], d1);
            }
        }
    }
}

// ---------------- layer-1 aggregation: single pass, fp16 gather, fp16 H1 out ----------------
__global__ __launch_bounds__(256) void k_agg1(const float* __restrict__ bias) {
    int w = (blockIdx.x * blockDim.x + threadIdx.x) >> 5;
    int lane = threadIdx.x & 31;
    if (w >= NN) return;
    int start = g_rowptr[w], end = g_rowptr[w + 1];
    int head = lane >> 3;
    float4 ad4 = *(const float4*)&g_ad1[w * 4];
    float adh = (head == 0) ? ad4.x : (head == 1) ? ad4.y : (head == 2) ? ad4.z : ad4.w;

    float den = 0.f;
    float acc0 = 0.f, acc1 = 0.f, acc2 = 0.f, acc3 = 0.f;
    float acc4 = 0.f, acc5 = 0.f, acc6 = 0.f, acc7 = 0.f;
    int p = start;
    for (; p + 1 < end; p += 2) {
        int sA = g_esrc[p];
        int sB = g_esrc[p + 1];
        float lA = g_as1[sA * 4 + head];
        float lB = g_as1[sB * 4 + head];
        uint4 ua = *(const uint4*)&g_xh1h[(size_t)sA * D1 + lane * 8];
        uint4 ub = *(const uint4*)&g_xh1h[(size_t)sB * D1 + lane * 8];
        float gA = __expf(lrelu(lA + adh));
        float gB = __expf(lrelu(lB + adh));
        den += gA + gB;
        float2 a0 = __half22float2(*(__half2*)&ua.x);
        float2 a1 = __half22float2(*(__half2*)&ua.y);
        float2 a2 = __half22float2(*(__half2*)&ua.z);
        float2 a3 = __half22float2(*(__half2*)&ua.w);
        float2 b0 = __half22float2(*(__half2*)&ub.x);
        float2 b1 = __half22float2(*(__half2*)&ub.y);
        float2 b2 = __half22float2(*(__half2*)&ub.z);
        float2 b3 = __half22float2(*(__half2*)&ub.w);
        acc0 += gA * a0.x + gB * b0.x; acc1 += gA * a0.y + gB * b0.y;
        acc2 += gA * a1.x + gB * b1.x; acc3 += gA * a1.y + gB * b1.y;
        acc4 += gA * a2.x + gB * b2.x; acc5 += gA * a2.y + gB * b2.y;
        acc6 += gA * a3.x + gB * b3.x; acc7 += gA * a3.y + gB * b3.y;
    }
    if (p < end) {
        int sA = g_esrc[p];
        float gA = __expf(lrelu(g_as1[sA * 4 + head] + adh));
        uint4 ua = *(const uint4*)&g_xh1h[(size_t)sA * D1 + lane * 8];
        den += gA;
        float2 a0 = __half22float2(*(__half2*)&ua.x);
        float2 a1 = __half22float2(*(__half2*)&ua.y);
        float2 a2 = __half22float2(*(__half2*)&ua.z);
        float2 a3 = __half22float2(*(__half2*)&ua.w);
        acc0 += gA * a0.x; acc1 += gA * a0.y;
        acc2 += gA * a1.x; acc3 += gA * a1.y;
        acc4 += gA * a2.x; acc5 += gA * a2.y;
        acc6 += gA * a3.x; acc7 += gA * a3.y;
    }
    float inv = 1.0f / den;
    const float4* bp = (const float4*)&bias[lane * 8];
    float4 b0 = bp[0], b1v = bp[1];
    __half2 o0 = __floats2half2_rn(acc0 * inv + b0.x,  acc1 * inv + b0.y);
    __half2 o1 = __floats2half2_rn(acc2 * inv + b0.z,  acc3 * inv + b0.w);
    __half2 o2 = __floats2half2_rn(acc4 * inv + b1v.x, acc5 * inv + b1v.y);
    __half2 o3 = __floats2half2_rn(acc6 * inv + b1v.z, acc7 * inv + b1v.w);
    *(uint4*)&g_h1f16[(size_t)w * D1 + lane * 8] =
        make_uint4(*(uint32_t*)&o0, *(uint32_t*)&o1, *(uint32_t*)&o2, *(uint32_t*)&o3);
}

// ---------------- layer-2 aggregation: single pass, fp16 gather, fp32 out ----------------
__global__ __launch_bounds__(256) void k_agg2(const float* __restrict__ bias,
                                              float* __restrict__ out) {
    int w = (blockIdx.x * blockDim.x + threadIdx.x) >> 5;
    int lane = threadIdx.x & 31;
    if (w >= NN) return;
    int start = g_rowptr[w], end = g_rowptr[w + 1];
    float ad = g_ad2[w];

    float den = 0.f;
    float acc0 = 0.f, acc1 = 0.f, acc2 = 0.f, acc3 = 0.f;
    int p = start;
    for (; p + 1 < end; p += 2) {
        int sA = g_esrc[p];
        int sB = g_esrc[p + 1];
        float lA = g_as2[sA];
        float lB = g_as2[sB];
        uint2 ua = *(const uint2*)&g_xh2h[(size_t)sA * D2 + lane * 4];
        uint2 ub = *(const uint2*)&g_xh2h[(size_t)sB * D2 + lane * 4];
        float gA = __expf(lrelu(lA + ad));
        float gB = __expf(lrelu(lB + ad));
        den += gA + gB;
        float2 a01 = __half22float2(*(__half2*)&ua.x);
        float2 a23 = __half22float2(*(__half2*)&ua.y);
        float2 b01 = __half22float2(*(__half2*)&ub.x);
        float2 b23 = __half22float2(*(__half2*)&ub.y);
        acc0 += gA * a01.x + gB * b01.x; acc1 += gA * a01.y + gB * b01.y;
        acc2 += gA * a23.x + gB * b23.x; acc3 += gA * a23.y + gB * b23.y;
    }
    if (p < end) {
        int sA = g_esrc[p];
        float gA = __expf(lrelu(g_as2[sA] + ad));
        uint2 ua = *(const uint2*)&g_xh2h[(size_t)sA * D2 + lane * 4];
        den += gA;
        float2 a01 = __half22float2(*(__half2*)&ua.x);
        float2 a23 = __half22float2(*(__half2*)&ua.y);
        acc0 += gA * a01.x; acc1 += gA * a01.y;
        acc2 += gA * a23.x; acc3 += gA * a23.y;
    }
    float inv = 1.0f / den;
    float4 b = *(const float4*)&bias[lane * 4];
    *(float4*)&out[(size_t)w * D2 + lane * 4] =
        make_float4(acc0 * inv + b.x, acc1 * inv + b.y, acc2 * inv + b.z, acc3 * inv + b.w);
}

// ---------------- host launch ----------------
extern "C" void kernel_launch(void* const* d_in, const int* in_sizes, int n_in,
                              void* d_out, int out_size) {
    const float* X    = (const float*)d_in[0];
    const int*   ei   = (const int*)  d_in[1];
    const float* W1   = (const float*)d_in[2];
    const float* as1  = (const float*)d_in[3];
    const float* ad1  = (const float*)d_in[4];
    const float* b1   = (const float*)d_in[5];
    const float* W2   = (const float*)d_in[6];
    const float* as2  = (const float*)d_in[7];
    const float* ad2  = (const float*)d_in[8];
    const float* b2   = (const float*)d_in[9];
    float* out = (float*)d_out;

    __half *p_xh1, *p_xh2, *p_xf, *p_h1f, *p_w1f, *p_w2f;
    float *p_as1, *p_ad1, *p_as2, *p_ad2;
    cudaGetSymbolAddress((void**)&p_xh1, g_xh1h);
    cudaGetSymbolAddress((void**)&p_xh2, g_xh2h);
    cudaGetSymbolAddress((void**)&p_xf,  g_xf16);
    cudaGetSymbolAddress((void**)&p_h1f, g_h1f16);
    cudaGetSymbolAddress((void**)&p_w1f, g_wt1f);
    cudaGetSymbolAddress((void**)&p_w2f, g_wt2f);
    cudaGetSymbolAddress((void**)&p_as1, g_as1);
    cudaGetSymbolAddress((void**)&p_ad1, g_ad1);
    cudaGetSymbolAddress((void**)&p_as2, g_as2);
    cudaGetSymbolAddress((void**)&p_ad2, g_ad2);

    const int SMEM_GEMM = 2 * 2 * TILE_ELEMS * 2;   // 40960 bytes
    cudaFuncSetAttribute(k_gemm_f16<64, 4>,  cudaFuncAttributeMaxDynamicSharedMemorySize, SMEM_GEMM);
    cudaFuncSetAttribute(k_gemm_f16<256, 1>, cudaFuncAttributeMaxDynamicSharedMemorySize, SMEM_GEMM);

    const int SCAN_BLOCKS = (NN + 1023) / 1024;   // 49
    const int NODE_BLOCKS = (NN + 7) / 8;
    const int M_BLOCKS = (NN + 127) / 128;        // 391
    const int EDGE_BLOCKS = (ET + 255) / 256;
    const int PREP_BLOCKS = (NN * 16 + 255) / 256;

    cudaStream_t s2;
    cudaStreamCreate(&s2);
    cudaEvent_t evFork, evJoin;
    cudaEventCreateWithFlags(&evFork, cudaEventDisableTiming);
    cudaEventCreateWithFlags(&evJoin, cudaEventDisableTiming);

    // main stream: prep (zeroes deg + logits, converts X/W)
    k_prep<<<PREP_BLOCKS, 256>>>(X, W1, W2);
    cudaEventRecord(evFork, 0);
    cudaStreamWaitEvent(s2, evFork, 0);

    // side stream: CSR build chain
    k_count<<<EDGE_BLOCKS, 256, 0, s2>>>(ei);
    k_scan1<<<SCAN_BLOCKS, 1024, 0, s2>>>();
    k_scan3<<<SCAN_BLOCKS, 1024, 0, s2>>>();
    k_fill<<<EDGE_BLOCKS, 256, 0, s2>>>(ei);
    cudaEventRecord(evJoin, s2);

    // main stream: gemm1 with fused attn1 logits
    k_gemm_f16<64, 4><<<dim3(D1 / 128, M_BLOCKS), 256, SMEM_GEMM>>>(
        p_xf, p_w1f, p_xh1, as1, ad1, p_as1, p_ad1, NN, D1);

    // join: agg1 needs CSR + logits
    cudaStreamWaitEvent(0, evJoin, 0);
    k_agg1<<<NODE_BLOCKS, 256>>>(b1);
    k_gemm_f16<256, 1><<<dim3(D2 / 128, M_BLOCKS), 256, SMEM_GEMM>>>(
        p_h1f, p_w2f, p_xh2, as2, ad2, p_as2, p_ad2, NN, D2);
    k_agg2<<<NODE_BLOCKS, 256>>>(b2, out);

    cudaEventDestroy(evFork);
    cudaEventDestroy(evJoin);
    cudaStreamDestroy(s2);
}

// round 16
// speedup vs baseline: 1.3610x; 1.3610x over previous
#include <cuda_runtime.h>
#include <cuda_bf16.h>
#include <cuda_fp16.h>
#include <cstdint>

#define NN 50000
#define NE 800000
#define ET 850000   // NE + NN self loops
#define D1 256      // heads(4) * h1(64)
#define D2 128
#define NCHUNK0 25088          // 196 * 128, row-chunk boundary
#define MB0 196                // gemm2 chunk-0 M blocks
#define MB1 195                // gemm2 chunk-1 M blocks (195*128 >= 24912)

// ---------------- device scratch (static; no runtime allocation) ----------------
__device__ __align__(16) __half g_xh1h[NN * D1];   // X @ W1 (fp16)
__device__ __align__(16) __half g_xh2h[NN * D2];   // H1 @ W2 (fp16)
__device__ __align__(16) __half g_xf16[NN * 64];    // X as fp16 (gemm1 A)
__device__ __align__(16) __half g_h1f16[NN * D1];   // H1 as fp16 (gemm2 A)
__device__ __align__(16) float g_as1[NN * 4];
__device__ __align__(16) float g_ad1[NN * 4];
__device__ float g_as2[NN];
__device__ float g_ad2[NN];
__device__ int g_deg[NN];
__device__ int g_rowptr[NN + 1];
__device__ int g_rank[ET];
__device__ int g_esrc[ET];
__device__ int g_bsum[64];
// transposed fp16 weights: Wt[n][k]
__device__ __align__(16) __half g_wt1f[D1 * 64];
__device__ __align__(16) __half g_wt2f[D2 * D1];

__device__ __forceinline__ int esrc_of(const int* __restrict__ ei, int e) {
    return e < NE ? ei[e] : e - NE;
}
__device__ __forceinline__ int edst_of(const int* __restrict__ ei, int e) {
    return e < NE ? ei[NE + e] : e - NE;
}
__device__ __forceinline__ float lrelu(float x) { return x > 0.f ? x : 0.2f * x; }

// ---------------- fused prep: zero_deg + X fp16 + W1/W2 transpose fp16 ----------------
__global__ __launch_bounds__(256) void k_prep(const float* __restrict__ X,
                                              const float* __restrict__ W1,
                                              const float* __restrict__ W2) {
    int i = blockIdx.x * 256 + threadIdx.x;
    if (i < NN) g_deg[i] = 0;
    if (i < NN * 16) {
        float4 v = ((const float4*)X)[i];
        __half2 h0 = __floats2half2_rn(v.x, v.y);
        __half2 h1 = __floats2half2_rn(v.z, v.w);
        ((uint2*)g_xf16)[i] = make_uint2(*(uint32_t*)&h0, *(uint32_t*)&h1);
    }
    if (i < 64 * D1) {
        int k = i / D1, n = i % D1;
        g_wt1f[n * 64 + k] = __float2half(W1[i]);
    }
    if (i < D1 * D2) {
        int k = i / D2, n = i % D2;
        g_wt2f[n * D1 + k] = __float2half(W2[i]);
    }
}

// ---------------- CSR build ----------------
__global__ void k_count(const int* __restrict__ ei) {
    int e = blockIdx.x * 256 + threadIdx.x;
    if (e < ET) {
        int r = atomicAdd(&g_deg[edst_of(ei, e)], 1);
        g_rank[e] = r;
    }
}

__global__ void k_scan1() {
    __shared__ int s[1024];
    int t = threadIdx.x;
    int i = blockIdx.x * 1024 + t;
    int v = (i < NN) ? g_deg[i] : 0;
    s[t] = v;
    __syncthreads();
    #pragma unroll
    for (int off = 1; off < 1024; off <<= 1) {
        int x = (t >= off) ? s[t - off] : 0;
        __syncthreads();
        s[t] += x;
        __syncthreads();
    }
    if (i < NN) g_rowptr[i] = s[t] - v;
    if (t == 1023) g_bsum[blockIdx.x] = s[t];
}

// scan3 folds the 49-element bsum prefix (verified R14)
__global__ void k_scan3() {
    __shared__ int soff;
    if (threadIdx.x == 0) {
        int a = 0;
        for (int b = 0; b < (int)blockIdx.x; b++) a += g_bsum[b];
        soff = a;
    }
    __syncthreads();
    int i = blockIdx.x * 1024 + threadIdx.x;
    if (i < NN)
        g_rowptr[i] = g_rowptr[i] + soff;
    if (i == 0) g_rowptr[NN] = ET;
}

__global__ void k_fill(const int* __restrict__ ei) {
    int e = blockIdx.x * 256 + threadIdx.x;
    if (e < ET) {
        int d = edst_of(ei, e);
        int s = esrc_of(ei, e);
        g_esrc[g_rowptr[d] + g_rank[e]] = s;
    }
}

// ---------------- HMMA fp16 GEMM, 2-stage cp.async pipeline (R11/R13-proven) ----------------
#define KC 32
#define ASTR 40
#define TILE_ELEMS (128 * ASTR)

__device__ __forceinline__ void ldsm4h(uint32_t& r0, uint32_t& r1, uint32_t& r2, uint32_t& r3,
                                       const __half* p) {
    uint32_t a = (uint32_t)__cvta_generic_to_shared(p);
    asm volatile("ldmatrix.sync.aligned.m8n8.x4.shared.b16 {%0,%1,%2,%3}, [%4];"
                 : "=r"(r0), "=r"(r1), "=r"(r2), "=r"(r3) : "r"(a));
}
__device__ __forceinline__ void mmaf16(float* d, uint32_t a0, uint32_t a1, uint32_t a2,
                                       uint32_t a3, uint32_t b0, uint32_t b1) {
    asm volatile(
        "mma.sync.aligned.m16n8k16.row.col.f32.f16.f16.f32 "
        "{%0,%1,%2,%3}, {%4,%5,%6,%7}, {%8,%9}, {%0,%1,%2,%3};"
        : "+f"(d[0]), "+f"(d[1]), "+f"(d[2]), "+f"(d[3])
        : "r"(a0), "r"(a1), "r"(a2), "r"(a3), "r"(b0), "r"(b1));
}
__device__ __forceinline__ void cpa16h(__half* dst, const __half* src) {
    uint32_t d = (uint32_t)__cvta_generic_to_shared(dst);
    asm volatile("cp.async.cg.shared.global [%0], [%1], 16;" :: "r"(d), "l"(src));
}

template<int KTOT>
__global__ __launch_bounds__(256, 2) void k_gemm_f16(const __half* __restrict__ A,
                                                     const __half* __restrict__ Bt,
                                                     __half* __restrict__ C,
                                                     int M, int NCOL, int by_off) {
    constexpr int NCH = KTOT / KC;
    extern __shared__ __half smh[];

    int tid = threadIdx.x;
    int wid = tid >> 5, lane = tid & 31;
    int g = lane >> 2, tig = lane & 3;
    int wm = (wid >> 2) * 64;
    int wn = (wid & 3) * 32;
    int bm = (blockIdx.y + by_off) * 128;
    int bn = blockIdx.x * 128;

    float acc[4][4][4];
    #pragma unroll
    for (int mt = 0; mt < 4; mt++)
        #pragma unroll
        for (int nt = 0; nt < 4; nt++)
            #pragma unroll
            for (int f = 0; f < 4; f++) acc[mt][nt][f] = 0.f;

    int a_r = lane & 15, a_c = (lane >> 4) * 8;
    int b_r = (lane >> 4) * 8 + (lane & 7), b_c = ((lane >> 3) & 1) * 8;

    int frow0 = tid >> 2, fcol = (tid & 3) * 8;
    int frow1 = (tid + 256) >> 2;

    auto fill = [&](int s, int c) {
        __half* s_a = smh + (s * 2 + 0) * TILE_ELEMS;
        __half* s_b = smh + (s * 2 + 1) * TILE_ELEMS;
        int kbase = c * KC;
        int ar0 = bm + frow0; if (ar0 >= M) ar0 = M - 1;
        int ar1 = bm + frow1; if (ar1 >= M) ar1 = M - 1;
        cpa16h(&s_a[frow0 * ASTR + fcol], &A[(size_t)ar0 * KTOT + kbase + fcol]);
        cpa16h(&s_a[frow1 * ASTR + fcol], &A[(size_t)ar1 * KTOT + kbase + fcol]);
        cpa16h(&s_b[frow0 * ASTR + fcol], &Bt[(size_t)(bn + frow0) * KTOT + kbase + fcol]);
        cpa16h(&s_b[frow1 * ASTR + fcol], &Bt[(size_t)(bn + frow1) * KTOT + kbase + fcol]);
        asm volatile("cp.async.commit_group;");
    };

    fill(0, 0);
    int stage = 0;
    for (int c = 0; c < NCH; c++) {
        if (c + 1 < NCH) {
            fill(stage ^ 1, c + 1);
            asm volatile("cp.async.wait_group 1;");
        } else {
            asm volatile("cp.async.wait_group 0;");
        }
        __syncthreads();

        __half* s_a = smh + (stage * 2 + 0) * TILE_ELEMS;
        __half* s_b = smh + (stage * 2 + 1) * TILE_ELEMS;

        #pragma unroll
        for (int ks = 0; ks < KC; ks += 16) {
            uint32_t bf[4][2];
            #pragma unroll
            for (int p = 0; p < 2; p++)
                ldsm4h(bf[2*p][0], bf[2*p][1], bf[2*p+1][0], bf[2*p+1][1],
                       &s_b[(wn + p * 16 + b_r) * ASTR + ks + b_c]);
            #pragma unroll
            for (int mt = 0; mt < 4; mt++) {
                uint32_t a0, a1, a2, a3;
                ldsm4h(a0, a1, a2, a3, &s_a[(wm + mt * 16 + a_r) * ASTR + ks + a_c]);
                #pragma unroll
                for (int nt = 0; nt < 4; nt++)
                    mmaf16(acc[mt][nt], a0, a1, a2, a3, bf[nt][0], bf[nt][1]);
            }
        }
        __syncthreads();
        stage ^= 1;
    }

    #pragma unroll
    for (int mt = 0; mt < 4; mt++) {
        int r0 = bm + wm + mt * 16 + g;
        int r1 = r0 + 8;
        #pragma unroll
        for (int nt = 0; nt < 4; nt++) {
            int col = bn + wn + nt * 8 + 2 * tig;
            if (r0 < M) {
                __half2 h = __floats2half2_rn(acc[mt][nt][0], acc[mt][nt][1]);
                *(uint32_t*)&C[(size_t)r0 * NCOL + col] = *(uint32_t*)&h;
            }
            if (r1 < M) {
                __half2 h = __floats2half2_rn(acc[mt][nt][2], acc[mt][nt][3]);
                *(uint32_t*)&C[(size_t)r1 * NCOL + col] = *(uint32_t*)&h;
            }
        }
    }
}

// ---------------- attention logit vectors (fp16 features) ----------------
__global__ __launch_bounds__(256) void k_attn1(const float* __restrict__ att_s,
                                               const float* __restrict__ att_d) {
    int w = (blockIdx.x * blockDim.x + threadIdx.x) >> 5;
    int lane = threadIdx.x & 31;
    if (w >= NN) return;
    uint4 u = *(const uint4*)&g_xh1h[(size_t)w * D1 + lane * 8];
    float2 f0 = __half22float2(*(__half2*)&u.x);
    float2 f1 = __half22float2(*(__half2*)&u.y);
    float2 f2 = __half22float2(*(__half2*)&u.z);
    float2 f3 = __half22float2(*(__half2*)&u.w);
    const float4* ap = (const float4*)&att_s[lane * 8];
    float4 a0 = ap[0], a1 = ap[1];
    const float4* dp = (const float4*)&att_d[lane * 8];
    float4 d0 = dp[0], d1 = dp[1];
    float ss = f0.x*a0.x + f0.y*a0.y + f1.x*a0.z + f1.y*a0.w
             + f2.x*a1.x + f2.y*a1.y + f3.x*a1.z + f3.y*a1.w;
    float sd = f0.x*d0.x + f0.y*d0.y + f1.x*d0.z + f1.y*d0.w
             + f2.x*d1.x + f2.y*d1.y + f3.x*d1.z + f3.y*d1.w;
    #pragma unroll
    for (int m = 1; m < 8; m <<= 1) {
        ss += __shfl_xor_sync(0xffffffffu, ss, m);
        sd += __shfl_xor_sync(0xffffffffu, sd, m);
    }
    if ((lane & 7) == 0) {
        int h = lane >> 3;
        g_as1[w * 4 + h] = ss;
        g_ad1[w * 4 + h] = sd;
    }
}

__global__ __launch_bounds__(256) void k_attn2(const float* __restrict__ att_s,
                                               const float* __restrict__ att_d,
                                               int node_off, int ncount) {
    int w = node_off + ((blockIdx.x * blockDim.x + threadIdx.x) >> 5);
    int lane = threadIdx.x & 31;
    if (w >= node_off + ncount || w >= NN) return;
    uint2 u = *(const uint2*)&g_xh2h[(size_t)w * D2 + lane * 4];
    float2 f0 = __half22float2(*(__half2*)&u.x);
    float2 f1 = __half22float2(*(__half2*)&u.y);
    float4 a = *(const float4*)&att_s[lane * 4];
    float4 d = *(const float4*)&att_d[lane * 4];
    float ss = f0.x*a.x + f0.y*a.y + f1.x*a.z + f1.y*a.w;
    float sd = f0.x*d.x + f0.y*d.y + f1.x*d.z + f1.y*d.w;
    #pragma unroll
    for (int m = 1; m < 32; m <<= 1) {
        ss += __shfl_xor_sync(0xffffffffu, ss, m);
        sd += __shfl_xor_sync(0xffffffffu, sd, m);
    }
    if (lane == 0) { g_as2[w] = ss; g_ad2[w] = sd; }
}

// ---------------- layer-1 aggregation (chunked): single pass, fp16 gather, fp16 H1 out ----
__global__ __launch_bounds__(256) void k_agg1(const float* __restrict__ bias,
                                              int node_off, int ncount) {
    int w = node_off + ((blockIdx.x * blockDim.x + threadIdx.x) >> 5);
    int lane = threadIdx.x & 31;
    if (w >= node_off + ncount || w >= NN) return;
    int start = g_rowptr[w], end = g_rowptr[w + 1];
    int head = lane >> 3;
    float4 ad4 = *(const float4*)&g_ad1[w * 4];
    float adh = (head == 0) ? ad4.x : (head == 1) ? ad4.y : (head == 2) ? ad4.z : ad4.w;

    float den = 0.f;
    float acc0 = 0.f, acc1 = 0.f, acc2 = 0.f, acc3 = 0.f;
    float acc4 = 0.f, acc5 = 0.f, acc6 = 0.f, acc7 = 0.f;
    int p = start;
    for (; p + 1 < end; p += 2) {
        int sA = g_esrc[p];
        int sB = g_esrc[p + 1];
        float lA = g_as1[sA * 4 + head];
        float lB = g_as1[sB * 4 + head];
        uint4 ua = *(const uint4*)&g_xh1h[(size_t)sA * D1 + lane * 8];
        uint4 ub = *(const uint4*)&g_xh1h[(size_t)sB * D1 + lane * 8];
        float gA = __expf(lrelu(lA + adh));
        float gB = __expf(lrelu(lB + adh));
        den += gA + gB;
        float2 a0 = __half22float2(*(__half2*)&ua.x);
        float2 a1 = __half22float2(*(__half2*)&ua.y);
        float2 a2 = __half22float2(*(__half2*)&ua.z);
        float2 a3 = __half22float2(*(__half2*)&ua.w);
        float2 b0 = __half22float2(*(__half2*)&ub.x);
        float2 b1 = __half22float2(*(__half2*)&ub.y);
        float2 b2 = __half22float2(*(__half2*)&ub.z);
        float2 b3 = __half22float2(*(__half2*)&ub.w);
        acc0 += gA * a0.x + gB * b0.x; acc1 += gA * a0.y + gB * b0.y;
        acc2 += gA * a1.x + gB * b1.x; acc3 += gA * a1.y + gB * b1.y;
        acc4 += gA * a2.x + gB * b2.x; acc5 += gA * a2.y + gB * b2.y;
        acc6 += gA * a3.x + gB * b3.x; acc7 += gA * a3.y + gB * b3.y;
    }
    if (p < end) {
        int sA = g_esrc[p];
        float gA = __expf(lrelu(g_as1[sA * 4 + head] + adh));
        uint4 ua = *(const uint4*)&g_xh1h[(size_t)sA * D1 + lane * 8];
        den += gA;
        float2 a0 = __half22float2(*(__half2*)&ua.x);
        float2 a1 = __half22float2(*(__half2*)&ua.y);
        float2 a2 = __half22float2(*(__half2*)&ua.z);
        float2 a3 = __half22float2(*(__half2*)&ua.w);
        acc0 += gA * a0.x; acc1 += gA * a0.y;
        acc2 += gA * a1.x; acc3 += gA * a1.y;
        acc4 += gA * a2.x; acc5 += gA * a2.y;
        acc6 += gA * a3.x; acc7 += gA * a3.y;
    }
    float inv = 1.0f / den;
    const float4* bp = (const float4*)&bias[lane * 8];
    float4 b0 = bp[0], b1v = bp[1];
    __half2 o0 = __floats2half2_rn(acc0 * inv + b0.x,  acc1 * inv + b0.y);
    __half2 o1 = __floats2half2_rn(acc2 * inv + b0.z,  acc3 * inv + b0.w);
    __half2 o2 = __floats2half2_rn(acc4 * inv + b1v.x, acc5 * inv + b1v.y);
    __half2 o3 = __floats2half2_rn(acc6 * inv + b1v.z, acc7 * inv + b1v.w);
    *(uint4*)&g_h1f16[(size_t)w * D1 + lane * 8] =
        make_uint4(*(uint32_t*)&o0, *(uint32_t*)&o1, *(uint32_t*)&o2, *(uint32_t*)&o3);
}

// ---------------- layer-2 aggregation: single pass, fp16 gather, fp32 out ----------------
__global__ __launch_bounds__(256) void k_agg2(const float* __restrict__ bias,
                                              float* __restrict__ out) {
    int w = (blockIdx.x * blockDim.x + threadIdx.x) >> 5;
    int lane = threadIdx.x & 31;
    if (w >= NN) return;
    int start = g_rowptr[w], end = g_rowptr[w + 1];
    float ad = g_ad2[w];

    float den = 0.f;
    float acc0 = 0.f, acc1 = 0.f, acc2 = 0.f, acc3 = 0.f;
    int p = start;
    for (; p + 1 < end; p += 2) {
        int sA = g_esrc[p];
        int sB = g_esrc[p + 1];
        float lA = g_as2[sA];
        float lB = g_as2[sB];
        uint2 ua = *(const uint2*)&g_xh2h[(size_t)sA * D2 + lane * 4];
        uint2 ub = *(const uint2*)&g_xh2h[(size_t)sB * D2 + lane * 4];
        float gA = __expf(lrelu(lA + ad));
        float gB = __expf(lrelu(lB + ad));
        den += gA + gB;
        float2 a01 = __half22float2(*(__half2*)&ua.x);
        float2 a23 = __half22float2(*(__half2*)&ua.y);
        float2 b01 = __half22float2(*(__half2*)&ub.x);
        float2 b23 = __half22float2(*(__half2*)&ub.y);
        acc0 += gA * a01.x + gB * b01.x; acc1 += gA * a01.y + gB * b01.y;
        acc2 += gA * a23.x + gB * b23.x; acc3 += gA * a23.y + gB * b23.y;
    }
    if (p < end) {
        int sA = g_esrc[p];
        float gA = __expf(lrelu(g_as2[sA] + ad));
        uint2 ua = *(const uint2*)&g_xh2h[(size_t)sA * D2 + lane * 4];
        den += gA;
        float2 a01 = __half22float2(*(__half2*)&ua.x);
        float2 a23 = __half22float2(*(__half2*)&ua.y);
        acc0 += gA * a01.x; acc1 += gA * a01.y;
        acc2 += gA * a23.x; acc3 += gA * a23.y;
    }
    float inv = 1.0f / den;
    float4 b = *(const float4*)&bias[lane * 4];
    *(float4*)&out[(size_t)w * D2 + lane * 4] =
        make_float4(acc0 * inv + b.x, acc1 * inv + b.y, acc2 * inv + b.z, acc3 * inv + b.w);
}

// ---------------- host launch ----------------
extern "C" void kernel_launch(void* const* d_in, const int* in_sizes, int n_in,
                              void* d_out, int out_size) {
    const float* X    = (const float*)d_in[0];
    const int*   ei   = (const int*)  d_in[1];
    const float* W1   = (const float*)d_in[2];
    const float* as1  = (const float*)d_in[3];
    const float* ad1  = (const float*)d_in[4];
    const float* b1   = (const float*)d_in[5];
    const float* W2   = (const float*)d_in[6];
    const float* as2  = (const float*)d_in[7];
    const float* ad2  = (const float*)d_in[8];
    const float* b2   = (const float*)d_in[9];
    float* out = (float*)d_out;

    __half *p_xh1, *p_xh2, *p_xf, *p_h1f, *p_w1f, *p_w2f;
    cudaGetSymbolAddress((void**)&p_xh1, g_xh1h);
    cudaGetSymbolAddress((void**)&p_xh2, g_xh2h);
    cudaGetSymbolAddress((void**)&p_xf,  g_xf16);
    cudaGetSymbolAddress((void**)&p_h1f, g_h1f16);
    cudaGetSymbolAddress((void**)&p_w1f, g_wt1f);
    cudaGetSymbolAddress((void**)&p_w2f, g_wt2f);

    const int SMEM_GEMM = 2 * 2 * TILE_ELEMS * 2;   // 40960 bytes
    cudaFuncSetAttribute(k_gemm_f16<64>,  cudaFuncAttributeMaxDynamicSharedMemorySize, SMEM_GEMM);
    cudaFuncSetAttribute(k_gemm_f16<256>, cudaFuncAttributeMaxDynamicSharedMemorySize, SMEM_GEMM);

    const int SCAN_BLOCKS = (NN + 1023) / 1024;   // 49
    const int NODE_BLOCKS = (NN + 7) / 8;
    const int M_BLOCKS = (NN + 127) / 128;        // 391
    const int EDGE_BLOCKS = (ET + 255) / 256;
    const int PREP_BLOCKS = (NN * 16 + 255) / 256;
    const int N0 = NCHUNK0, N1 = NN - NCHUNK0;
    const int AGG_BLOCKS0 = (N0 + 7) / 8;
    const int AGG_BLOCKS1 = (N1 + 7) / 8;

    cudaStream_t s2;
    cudaStreamCreate(&s2);
    cudaEvent_t evFork, evJoin, evA, evB;
    cudaEventCreateWithFlags(&evFork, cudaEventDisableTiming);
    cudaEventCreateWithFlags(&evJoin, cudaEventDisableTiming);
    cudaEventCreateWithFlags(&evA,    cudaEventDisableTiming);
    cudaEventCreateWithFlags(&evB,    cudaEventDisableTiming);

    // main: prep (zero deg, convert X/W)
    k_prep<<<PREP_BLOCKS, 256>>>(X, W1, W2);
    cudaEventRecord(evFork, 0);
    cudaStreamWaitEvent(s2, evFork, 0);

    // side: CSR chain
    k_count<<<EDGE_BLOCKS, 256, 0, s2>>>(ei);
    k_scan1<<<SCAN_BLOCKS, 1024, 0, s2>>>();
    k_scan3<<<SCAN_BLOCKS, 1024, 0, s2>>>();
    k_fill<<<EDGE_BLOCKS, 256, 0, s2>>>(ei);
    cudaEventRecord(evJoin, s2);

    // main: gemm1 -> attn1
    k_gemm_f16<64><<<dim3(D1 / 128, M_BLOCKS), 256, SMEM_GEMM>>>(p_xf, p_w1f, p_xh1, NN, D1, 0);
    k_attn1<<<NODE_BLOCKS, 256>>>(as1, ad1);

    // join CSR; pipelined agg1 / gemm2 / attn2
    cudaStreamWaitEvent(0, evJoin, 0);
    k_agg1<<<AGG_BLOCKS0, 256>>>(b1, 0, N0);                 // chunk 0
    cudaEventRecord(evA, 0);
    k_agg1<<<AGG_BLOCKS1, 256>>>(b1, N0, N1);                // chunk 1 (overlaps s2 gemm2_c0)

    cudaStreamWaitEvent(s2, evA, 0);
    k_gemm_f16<256><<<dim3(D2 / 128, MB0), 256, SMEM_GEMM, s2>>>(p_h1f, p_w2f, p_xh2, N0, D2, 0);
    k_attn2<<<(N0 * 32 + 255) / 256, 256, 0, s2>>>(as2, ad2, 0, N0);
    cudaEventRecord(evB, s2);

    k_gemm_f16<256><<<dim3(D2 / 128, MB1), 256, SMEM_GEMM>>>(p_h1f, p_w2f, p_xh2, NN, D2, MB0);
    k_attn2<<<(N1 * 32 + 255) / 256, 256>>>(as2, ad2, N0, N1);
    cudaStreamWaitEvent(0, evB, 0);
    k_agg2<<<NODE_BLOCKS, 256>>>(b2, out);

    cudaEventDestroy(evFork);
    cudaEventDestroy(evJoin);
    cudaEventDestroy(evA);
    cudaEventDestroy(evB);
    cudaStreamDestroy(s2);
}

// round 17
// speedup vs baseline: 1.3970x; 1.0265x over previous
#include <cuda_runtime.h>
#include <cuda_bf16.h>
#include <cuda_fp16.h>
#include <cstdint>

#define NN 50000
#define NE 800000
#define ET 850000   // NE + NN self loops
#define D1 256      // heads(4) * h1(64)
#define D2 128

// ---------------- device scratch (static; no runtime allocation) ----------------
__device__ __align__(16) __half g_xh1h[NN * D1];   // X @ W1 (fp16)
__device__ __align__(16) __half g_xh2h[NN * D2];   // H1 @ W2 (fp16)
__device__ __align__(16) __half g_xf16[NN * 64];    // X as fp16 (gemm1 A)
__device__ __align__(16) __half g_h1f16[NN * D1];   // H1 as fp16 (gemm2 A)
__device__ __align__(16) float g_as1[NN * 4];
__device__ __align__(16) float g_ad1[NN * 4];
__device__ float g_as2[NN];
__device__ float g_ad2[NN];
__device__ int g_deg[NN];
__device__ int g_rowptr[NN + 1];
__device__ int g_rank[ET];
__device__ int g_esrc[ET];
__device__ int g_bsum[64];
// transposed fp16 weights: Wt[n][k]
__device__ __align__(16) __half g_wt1f[D1 * 64];
__device__ __align__(16) __half g_wt2f[D2 * D1];

__device__ __forceinline__ int esrc_of(const int* __restrict__ ei, int e) {
    return e < NE ? ei[e] : e - NE;
}
__device__ __forceinline__ int edst_of(const int* __restrict__ ei, int e) {
    return e < NE ? ei[NE + e] : e - NE;
}
__device__ __forceinline__ float lrelu(float x) { return x > 0.f ? x : 0.2f * x; }

// ---------------- prep: X fp16 + W1/W2 transpose fp16 (deg zero moved to k_zero) ----------
__global__ __launch_bounds__(256) void k_prep(const float* __restrict__ X,
                                              const float* __restrict__ W1,
                                              const float* __restrict__ W2) {
    int i = blockIdx.x * 256 + threadIdx.x;
    if (i < NN * 16) {
        float4 v = ((const float4*)X)[i];
        __half2 h0 = __floats2half2_rn(v.x, v.y);
        __half2 h1 = __floats2half2_rn(v.z, v.w);
        ((uint2*)g_xf16)[i] = make_uint2(*(uint32_t*)&h0, *(uint32_t*)&h1);
    }
    if (i < 64 * D1) {
        int k = i / D1, n = i % D1;
        g_wt1f[n * 64 + k] = __float2half(W1[i]);
    }
    if (i < D1 * D2) {
        int k = i / D2, n = i % D2;
        g_wt2f[n * D1 + k] = __float2half(W2[i]);
    }
}

// ---------------- CSR build (runs on side stream from t=0) ----------------
__global__ void k_zero() {
    int i = blockIdx.x * 256 + threadIdx.x;
    if (i < NN) g_deg[i] = 0;
}

__global__ void k_count(const int* __restrict__ ei) {
    int e = blockIdx.x * 256 + threadIdx.x;
    if (e < ET) {
        int r = atomicAdd(&g_deg[edst_of(ei, e)], 1);
        g_rank[e] = r;
    }
}

__global__ void k_scan1() {
    __shared__ int s[1024];
    int t = threadIdx.x;
    int i = blockIdx.x * 1024 + t;
    int v = (i < NN) ? g_deg[i] : 0;
    s[t] = v;
    __syncthreads();
    #pragma unroll
    for (int off = 1; off < 1024; off <<= 1) {
        int x = (t >= off) ? s[t - off] : 0;
        __syncthreads();
        s[t] += x;
        __syncthreads();
    }
    if (i < NN) g_rowptr[i] = s[t] - v;
    if (t == 1023) g_bsum[blockIdx.x] = s[t];
}

// folded: computes its own 49-element bsum prefix (removes k_scan2 launch)
__global__ void k_scan3() {
    __shared__ int soff;
    if (threadIdx.x == 0) {
        int a = 0;
        for (int b = 0; b < (int)blockIdx.x; b++) a += g_bsum[b];
        soff = a;
    }
    __syncthreads();
    int i = blockIdx.x * 1024 + threadIdx.x;
    if (i < NN)
        g_rowptr[i] = g_rowptr[i] + soff;
    if (i == 0) g_rowptr[NN] = ET;
}

__global__ void k_fill(const int* __restrict__ ei) {
    int e = blockIdx.x * 256 + threadIdx.x;
    if (e < ET) {
        int d = edst_of(ei, e);
        int s = esrc_of(ei, e);
        g_esrc[g_rowptr[d] + g_rank[e]] = s;
    }
}

// ---------------- HMMA fp16 GEMM, 2-stage cp.async pipeline (R11/R13-proven) ----------------
#define KC 32
#define ASTR 40
#define TILE_ELEMS (128 * ASTR)

__device__ __forceinline__ void ldsm4h(uint32_t& r0, uint32_t& r1, uint32_t& r2, uint32_t& r3,
                                       const __half* p) {
    uint32_t a = (uint32_t)__cvta_generic_to_shared(p);
    asm volatile("ldmatrix.sync.aligned.m8n8.x4.shared.b16 {%0,%1,%2,%3}, [%4];"
                 : "=r"(r0), "=r"(r1), "=r"(r2), "=r"(r3) : "r"(a));
}
__device__ __forceinline__ void mmaf16(float* d, uint32_t a0, uint32_t a1, uint32_t a2,
                                       uint32_t a3, uint32_t b0, uint32_t b1) {
    asm volatile(
        "mma.sync.aligned.m16n8k16.row.col.f32.f16.f16.f32 "
        "{%0,%1,%2,%3}, {%4,%5,%6,%7}, {%8,%9}, {%0,%1,%2,%3};"
        : "+f"(d[0]), "+f"(d[1]), "+f"(d[2]), "+f"(d[3])
        : "r"(a0), "r"(a1), "r"(a2), "r"(a3), "r"(b0), "r"(b1));
}
__device__ __forceinline__ void cpa16h(__half* dst, const __half* src) {
    uint32_t d = (uint32_t)__cvta_generic_to_shared(dst);
    asm volatile("cp.async.cg.shared.global [%0], [%1], 16;" :: "r"(d), "l"(src));
}

template<int KTOT>
__global__ __launch_bounds__(256, 2) void k_gemm_f16(const __half* __restrict__ A,
                                                     const __half* __restrict__ Bt,
                                                     __half* __restrict__ C,
                                                     int M, int NCOL) {
    constexpr int NCH = KTOT / KC;
    extern __shared__ __half smh[];

    int tid = threadIdx.x;
    int wid = tid >> 5, lane = tid & 31;
    int g = lane >> 2, tig = lane & 3;
    int wm = (wid >> 2) * 64;
    int wn = (wid & 3) * 32;
    int bm = blockIdx.y * 128;
    int bn = blockIdx.x * 128;

    float acc[4][4][4];
    #pragma unroll
    for (int mt = 0; mt < 4; mt++)
        #pragma unroll
        for (int nt = 0; nt < 4; nt++)
            #pragma unroll
            for (int f = 0; f < 4; f++) acc[mt][nt][f] = 0.f;

    int a_r = lane & 15, a_c = (lane >> 4) * 8;
    int b_r = (lane >> 4) * 8 + (lane & 7), b_c = ((lane >> 3) & 1) * 8;

    int frow0 = tid >> 2, fcol = (tid & 3) * 8;
    int frow1 = (tid + 256) >> 2;

    auto fill = [&](int s, int c) {
        __half* s_a = smh + (s * 2 + 0) * TILE_ELEMS;
        __half* s_b = smh + (s * 2 + 1) * TILE_ELEMS;
        int kbase = c * KC;
        int ar0 = bm + frow0; if (ar0 >= M) ar0 = M - 1;
        int ar1 = bm + frow1; if (ar1 >= M) ar1 = M - 1;
        cpa16h(&s_a[frow0 * ASTR + fcol], &A[(size_t)ar0 * KTOT + kbase + fcol]);
        cpa16h(&s_a[frow1 * ASTR + fcol], &A[(size_t)ar1 * KTOT + kbase + fcol]);
        cpa16h(&s_b[frow0 * ASTR + fcol], &Bt[(size_t)(bn + frow0) * KTOT + kbase + fcol]);
        cpa16h(&s_b[frow1 * ASTR + fcol], &Bt[(size_t)(bn + frow1) * KTOT + kbase + fcol]);
        asm volatile("cp.async.commit_group;");
    };

    fill(0, 0);
    int stage = 0;
    for (int c = 0; c < NCH; c++) {
        if (c + 1 < NCH) {
            fill(stage ^ 1, c + 1);
            asm volatile("cp.async.wait_group 1;");
        } else {
            asm volatile("cp.async.wait_group 0;");
        }
        __syncthreads();

        __half* s_a = smh + (stage * 2 + 0) * TILE_ELEMS;
        __half* s_b = smh + (stage * 2 + 1) * TILE_ELEMS;

        #pragma unroll
        for (int ks = 0; ks < KC; ks += 16) {
            uint32_t bf[4][2];
            #pragma unroll
            for (int p = 0; p < 2; p++)
                ldsm4h(bf[2*p][0], bf[2*p][1], bf[2*p+1][0], bf[2*p+1][1],
                       &s_b[(wn + p * 16 + b_r) * ASTR + ks + b_c]);
            #pragma unroll
            for (int mt = 0; mt < 4; mt++) {
                uint32_t a0, a1, a2, a3;
                ldsm4h(a0, a1, a2, a3, &s_a[(wm + mt * 16 + a_r) * ASTR + ks + a_c]);
                #pragma unroll
                for (int nt = 0; nt < 4; nt++)
                    mmaf16(acc[mt][nt], a0, a1, a2, a3, bf[nt][0], bf[nt][1]);
            }
        }
        __syncthreads();
        stage ^= 1;
    }

    #pragma unroll
    for (int mt = 0; mt < 4; mt++) {
        int r0 = bm + wm + mt * 16 + g;
        int r1 = r0 + 8;
        #pragma unroll
        for (int nt = 0; nt < 4; nt++) {
            int col = bn + wn + nt * 8 + 2 * tig;
            if (r0 < M) {
                __half2 h = __floats2half2_rn(acc[mt][nt][0], acc[mt][nt][1]);
                *(uint32_t*)&C[(size_t)r0 * NCOL + col] = *(uint32_t*)&h;
            }
            if (r1 < M) {
                __half2 h = __floats2half2_rn(acc[mt][nt][2], acc[mt][nt][3]);
                *(uint32_t*)&C[(size_t)r1 * NCOL + col] = *(uint32_t*)&h;
            }
        }
    }
}

// ---------------- attention logit vectors (fp16 features) ----------------
__global__ __launch_bounds__(256) void k_attn1(const float* __restrict__ att_s,
                                               const float* __restrict__ att_d) {
    int w = (blockIdx.x * blockDim.x + threadIdx.x) >> 5;
    int lane = threadIdx.x & 31;
    if (w >= NN) return;
    uint4 u = *(const uint4*)&g_xh1h[(size_t)w * D1 + lane * 8];
    float2 f0 = __half22float2(*(__half2*)&u.x);
    float2 f1 = __half22float2(*(__half2*)&u.y);
    float2 f2 = __half22float2(*(__half2*)&u.z);
    float2 f3 = __half22float2(*(__half2*)&u.w);
    const float4* ap = (const float4*)&att_s[lane * 8];
    float4 a0 = ap[0], a1 = ap[1];
    const float4* dp = (const float4*)&att_d[lane * 8];
    float4 d0 = dp[0], d1 = dp[1];
    float ss = f0.x*a0.x + f0.y*a0.y + f1.x*a0.z + f1.y*a0.w
             + f2.x*a1.x + f2.y*a1.y + f3.x*a1.z + f3.y*a1.w;
    float sd = f0.x*d0.x + f0.y*d0.y + f1.x*d0.z + f1.y*d0.w
             + f2.x*d1.x + f2.y*d1.y + f3.x*d1.z + f3.y*d1.w;
    #pragma unroll
    for (int m = 1; m < 8; m <<= 1) {
        ss += __shfl_xor_sync(0xffffffffu, ss, m);
        sd += __shfl_xor_sync(0xffffffffu, sd, m);
    }
    if ((lane & 7) == 0) {
        int h = lane >> 3;
        g_as1[w * 4 + h] = ss;
        g_ad1[w * 4 + h] = sd;
    }
}

__global__ __launch_bounds__(256) void k_attn2(const float* __restrict__ att_s,
                                               const float* __restrict__ att_d) {
    int w = (blockIdx.x * blockDim.x + threadIdx.x) >> 5;
    int lane = threadIdx.x & 31;
    if (w >= NN) return;
    uint2 u = *(const uint2*)&g_xh2h[(size_t)w * D2 + lane * 4];
    float2 f0 = __half22float2(*(__half2*)&u.x);
    float2 f1 = __half22float2(*(__half2*)&u.y);
    float4 a = *(const float4*)&att_s[lane * 4];
    float4 d = *(const float4*)&att_d[lane * 4];
    float ss = f0.x*a.x + f0.y*a.y + f1.x*a.z + f1.y*a.w;
    float sd = f0.x*d.x + f0.y*d.y + f1.x*d.z + f1.y*d.w;
    #pragma unroll
    for (int m = 1; m < 32; m <<= 1) {
        ss += __shfl_xor_sync(0xffffffffu, ss, m);
        sd += __shfl_xor_sync(0xffffffffu, sd, m);
    }
    if (lane == 0) { g_as2[w] = ss; g_ad2[w] = sd; }
}

// ---------------- layer-1 aggregation: single pass, fp16 gather, fp16 H1 out ----------------
__global__ __launch_bounds__(256) void k_agg1(const float* __restrict__ bias) {
    int w = (blockIdx.x * blockDim.x + threadIdx.x) >> 5;
    int lane = threadIdx.x & 31;
    if (w >= NN) return;
    int start = g_rowptr[w], end = g_rowptr[w + 1];
    int head = lane >> 3;
    float4 ad4 = *(const float4*)&g_ad1[w * 4];
    float adh = (head == 0) ? ad4.x : (head == 1) ? ad4.y : (head == 2) ? ad4.z : ad4.w;

    float den = 0.f;
    float acc0 = 0.f, acc1 = 0.f, acc2 = 0.f, acc3 = 0.f;
    float acc4 = 0.f, acc5 = 0.f, acc6 = 0.f, acc7 = 0.f;
    int p = start;
    for (; p + 1 < end; p += 2) {
        int sA = g_esrc[p];
        int sB = g_esrc[p + 1];
        float lA = g_as1[sA * 4 + head];
        float lB = g_as1[sB * 4 + head];
        uint4 ua = *(const uint4*)&g_xh1h[(size_t)sA * D1 + lane * 8];
        uint4 ub = *(const uint4*)&g_xh1h[(size_t)sB * D1 + lane * 8];
        float gA = __expf(lrelu(lA + adh));
        float gB = __expf(lrelu(lB + adh));
        den += gA + gB;
        float2 a0 = __half22float2(*(__half2*)&ua.x);
        float2 a1 = __half22float2(*(__half2*)&ua.y);
        float2 a2 = __half22float2(*(__half2*)&ua.z);
        float2 a3 = __half22float2(*(__half2*)&ua.w);
        float2 b0 = __half22float2(*(__half2*)&ub.x);
        float2 b1 = __half22float2(*(__half2*)&ub.y);
        float2 b2 = __half22float2(*(__half2*)&ub.z);
        float2 b3 = __half22float2(*(__half2*)&ub.w);
        acc0 += gA * a0.x + gB * b0.x; acc1 += gA * a0.y + gB * b0.y;
        acc2 += gA * a1.x + gB * b1.x; acc3 += gA * a1.y + gB * b1.y;
        acc4 += gA * a2.x + gB * b2.x; acc5 += gA * a2.y + gB * b2.y;
        acc6 += gA * a3.x + gB * b3.x; acc7 += gA * a3.y + gB * b3.y;
    }
    if (p < end) {
        int sA = g_esrc[p];
        float gA = __expf(lrelu(g_as1[sA * 4 + head] + adh));
        uint4 ua = *(const uint4*)&g_xh1h[(size_t)sA * D1 + lane * 8];
        den += gA;
        float2 a0 = __half22float2(*(__half2*)&ua.x);
        float2 a1 = __half22float2(*(__half2*)&ua.y);
        float2 a2 = __half22float2(*(__half2*)&ua.z);
        float2 a3 = __half22float2(*(__half2*)&ua.w);
        acc0 += gA * a0.x; acc1 += gA * a0.y;
        acc2 += gA * a1.x; acc3 += gA * a1.y;
        acc4 += gA * a2.x; acc5 += gA * a2.y;
        acc6 += gA * a3.x; acc7 += gA * a3.y;
    }
    float inv = 1.0f / den;
    const float4* bp = (const float4*)&bias[lane * 8];
    float4 b0 = bp[0], b1v = bp[1];
    __half2 o0 = __floats2half2_rn(acc0 * inv + b0.x,  acc1 * inv + b0.y);
    __half2 o1 = __floats2half2_rn(acc2 * inv + b0.z,  acc3 * inv + b0.w);
    __half2 o2 = __floats2half2_rn(acc4 * inv + b1v.x, acc5 * inv + b1v.y);
    __half2 o3 = __floats2half2_rn(acc6 * inv + b1v.z, acc7 * inv + b1v.w);
    *(uint4*)&g_h1f16[(size_t)w * D1 + lane * 8] =
        make_uint4(*(uint32_t*)&o0, *(uint32_t*)&o1, *(uint32_t*)&o2, *(uint32_t*)&o3);
}

// ---------------- layer-2 aggregation: single pass, fp16 gather, fp32 out ----------------
__global__ __launch_bounds__(256) void k_agg2(const float* __restrict__ bias,
                                              float* __restrict__ out) {
    int w = (blockIdx.x * blockDim.x + threadIdx.x) >> 5;
    int lane = threadIdx.x & 31;
    if (w >= NN) return;
    int start = g_rowptr[w], end = g_rowptr[w + 1];
    float ad = g_ad2[w];

    float den = 0.f;
    float acc0 = 0.f, acc1 = 0.f, acc2 = 0.f, acc3 = 0.f;
    int p = start;
    for (; p + 1 < end; p += 2) {
        int sA = g_esrc[p];
        int sB = g_esrc[p + 1];
        float lA = g_as2[sA];
        float lB = g_as2[sB];
        uint2 ua = *(const uint2*)&g_xh2h[(size_t)sA * D2 + lane * 4];
        uint2 ub = *(const uint2*)&g_xh2h[(size_t)sB * D2 + lane * 4];
        float gA = __expf(lrelu(lA + ad));
        float gB = __expf(lrelu(lB + ad));
        den += gA + gB;
        float2 a01 = __half22float2(*(__half2*)&ua.x);
        float2 a23 = __half22float2(*(__half2*)&ua.y);
        float2 b01 = __half22float2(*(__half2*)&ub.x);
        float2 b23 = __half22float2(*(__half2*)&ub.y);
        acc0 += gA * a01.x + gB * b01.x; acc1 += gA * a01.y + gB * b01.y;
        acc2 += gA * a23.x + gB * b23.x; acc3 += gA * a23.y + gB * b23.y;
    }
    if (p < end) {
        int sA = g_esrc[p];
        float gA = __expf(lrelu(g_as2[sA] + ad));
        uint2 ua = *(const uint2*)&g_xh2h[(size_t)sA * D2 + lane * 4];
        den += gA;
        float2 a01 = __half22float2(*(__half2*)&ua.x);
        float2 a23 = __half22float2(*(__half2*)&ua.y);
        acc0 += gA * a01.x; acc1 += gA * a01.y;
        acc2 += gA * a23.x; acc3 += gA * a23.y;
    }
    float inv = 1.0f / den;
    float4 b = *(const float4*)&bias[lane * 4];
    *(float4*)&out[(size_t)w * D2 + lane * 4] =
        make_float4(acc0 * inv + b.x, acc1 * inv + b.y, acc2 * inv + b.z, acc3 * inv + b.w);
}

// ---------------- host launch ----------------
extern "C" void kernel_launch(void* const* d_in, const int* in_sizes, int n_in,
                              void* d_out, int out_size) {
    const float* X    = (const float*)d_in[0];
    const int*   ei   = (const int*)  d_in[1];
    const float* W1   = (const float*)d_in[2];
    const float* as1  = (const float*)d_in[3];
    const float* ad1  = (const float*)d_in[4];
    const float* b1   = (const float*)d_in[5];
    const float* W2   = (const float*)d_in[6];
    const float* as2  = (const float*)d_in[7];
    const float* ad2  = (const float*)d_in[8];
    const float* b2   = (const float*)d_in[9];
    float* out = (float*)d_out;

    __half *p_xh1, *p_xh2, *p_xf, *p_h1f, *p_w1f, *p_w2f;
    cudaGetSymbolAddress((void**)&p_xh1, g_xh1h);
    cudaGetSymbolAddress((void**)&p_xh2, g_xh2h);
    cudaGetSymbolAddress((void**)&p_xf,  g_xf16);
    cudaGetSymbolAddress((void**)&p_h1f, g_h1f16);
    cudaGetSymbolAddress((void**)&p_w1f, g_wt1f);
    cudaGetSymbolAddress((void**)&p_w2f, g_wt2f);

    const int SMEM_GEMM = 2 * 2 * TILE_ELEMS * 2;   // 40960 bytes
    cudaFuncSetAttribute(k_gemm_f16<64>,  cudaFuncAttributeMaxDynamicSharedMemorySize, SMEM_GEMM);
    cudaFuncSetAttribute(k_gemm_f16<256>, cudaFuncAttributeMaxDynamicSharedMemorySize, SMEM_GEMM);

    const int SCAN_BLOCKS = (NN + 1023) / 1024;   // 49
    const int NODE_BLOCKS = (NN + 7) / 8;
    const int M_BLOCKS = (NN + 127) / 128;        // 391
    const int EDGE_BLOCKS = (ET + 255) / 256;
    const int PREP_BLOCKS = (NN * 16 + 255) / 256;

    cudaStream_t s2;
    cudaStreamCreate(&s2);
    cudaEvent_t evFork, evJoin;
    cudaEventCreateWithFlags(&evFork, cudaEventDisableTiming);
    cudaEventCreateWithFlags(&evJoin, cudaEventDisableTiming);

    // fork immediately: side stream owns the full CSR chain from t=0
    cudaEventRecord(evFork, 0);
    cudaStreamWaitEvent(s2, evFork, 0);
    k_zero<<<(NN + 255) / 256, 256, 0, s2>>>();
    k_count<<<EDGE_BLOCKS, 256, 0, s2>>>(ei);
    k_scan1<<<SCAN_BLOCKS, 1024, 0, s2>>>();
    k_scan3<<<SCAN_BLOCKS, 1024, 0, s2>>>();
    k_fill<<<EDGE_BLOCKS, 256, 0, s2>>>(ei);
    cudaEventRecord(evJoin, s2);

    // main: prep (X/W converts) -> gemm1 -> attn1, concurrent with CSR
    k_prep<<<PREP_BLOCKS, 256>>>(X, W1, W2);
    k_gemm_f16<64><<<dim3(D1 / 128, M_BLOCKS), 256, SMEM_GEMM>>>(p_xf, p_w1f, p_xh1, NN, D1);
    k_attn1<<<NODE_BLOCKS, 256>>>(as1, ad1);

    // join: agg1 needs CSR + attn1
    cudaStreamWaitEvent(0, evJoin, 0);
    k_agg1<<<NODE_BLOCKS, 256>>>(b1);
    k_gemm_f16<256><<<dim3(D2 / 128, M_BLOCKS), 256, SMEM_GEMM>>>(p_h1f, p_w2f, p_xh2, NN, D2);
    k_attn2<<<NODE_BLOCKS, 256>>>(as2, ad2);
    k_agg2<<<NODE_BLOCKS, 256>>>(b2, out);

    cudaEventDestroy(evFork);
    cudaEventDestroy(evJoin);
    cudaStreamDestroy(s2);
}